// round 3
// baseline (speedup 1.0000x reference)
#include <cuda_runtime.h>
#include <math_constants.h>
#include <cstdint>

#define NROWS 16384
#define KCODES 8192
#define DIM 256
#define MT 128
#define NT 128
#define ZS_STRIDE 260   // 256 + 4 pad (float4-aligned, odd float4 stride -> no conflicts)
#define ES_STRIDE 68    // 64 + 4 pad (float4 stride 17, odd -> 2-way max)

__device__ int    g_codes[NROWS];
__device__ double g_part[NROWS];
__device__ float  g_e2[KCODES];

// ---------------------------------------------------------------------------
// e2[k] = sum_d emb[k][d]^2   (fp32; order-insensitive at the precision needed)
// ---------------------------------------------------------------------------
__global__ void e2_kernel(const float* __restrict__ emb) {
    int k    = blockIdx.x * 8 + (threadIdx.x >> 5);
    int lane = threadIdx.x & 31;
    const float* p = emb + (size_t)k * DIM;
    float s = 0.f;
#pragma unroll
    for (int i = 0; i < 8; i++) { float v = p[lane + 32 * i]; s = __fmaf_rn(v, v, s); }
#pragma unroll
    for (int o = 16; o; o >>= 1) s += __shfl_down_sync(0xffffffffu, s, o);
    if (lane == 0) g_e2[k] = s;
}

// ---------------------------------------------------------------------------
// Main: fused SGEMM + quantized-dist argmin (first-index tie-break).
// Grid: NROWS/MT blocks of 256 threads. Each CTA owns 128 rows, loops all K.
// ---------------------------------------------------------------------------
__global__ __launch_bounds__(256, 1)
void vq_main(const float* __restrict__ z_e, const float* __restrict__ emb) {
    extern __shared__ float sm[];
    float* zs  = sm;                          // [128][260]
    float* es  = sm + MT * ZS_STRIDE;         // [128][68]
    float* x2s = es + NT * ES_STRIDE;         // [128]

    const int tid = threadIdx.x;
    const int ty  = tid >> 4;                 // 0..15
    const int tx  = tid & 15;                 // 0..15
    const int n0  = blockIdx.x * MT;

    // Load resident z tile (coalesced, float4).
    {
        const float4* gz = (const float4*)(z_e + (size_t)n0 * DIM);
#pragma unroll
        for (int t = 0; t < (MT * DIM / 4) / 256; t++) {
            int idx4 = tid + t * 256;
            int row  = idx4 >> 6;
            int d4   = idx4 & 63;
            float4 v = gz[row * 64 + d4];
            *(float4*)&zs[row * ZS_STRIDE + 4 * d4] = v;
        }
    }
    __syncthreads();

    // x2 per row (fp32; binade-invariance makes exact order irrelevant).
    if (tid < MT) {
        const float* zr = &zs[tid * ZS_STRIDE];
        float s = 0.f;
        for (int d = 0; d < DIM; d++) s = __fmaf_rn(zr[d], zr[d], s);
        x2s[tid] = s;
    }
    __syncthreads();

    float rmin[8];
    int   rk[8];
#pragma unroll
    for (int i = 0; i < 8; i++) { rmin[i] = CUDART_INF_F; rk[i] = 0x7fffffff; }

    for (int k0 = 0; k0 < KCODES; k0 += NT) {
        float acc[8][8];
#pragma unroll
        for (int i = 0; i < 8; i++)
#pragma unroll
            for (int j = 0; j < 8; j++) acc[i][j] = 0.f;

        for (int c = 0; c < 4; c++) {         // d-chunks of 64
            __syncthreads();                  // protect es buffer reuse
            {
                const float4* ge = (const float4*)emb;
#pragma unroll
                for (int t = 0; t < 8; t++) {
                    int idx4 = tid + t * 256;        // 0..2047
                    int col  = idx4 >> 4;
                    int d4   = idx4 & 15;
                    float4 v = ge[(size_t)(k0 + col) * 64 + c * 16 + d4];
                    *(float4*)&es[col * ES_STRIDE + 4 * d4] = v;
                }
            }
            __syncthreads();

            const float* za = &zs[ty * ZS_STRIDE + c * 64];
            const float* eb = &es[tx * ES_STRIDE];
#pragma unroll 4
            for (int d4 = 0; d4 < 16; d4++) {
                float4 a[8], b[8];
#pragma unroll
                for (int i = 0; i < 8; i++)
                    a[i] = *(const float4*)&za[i * 16 * ZS_STRIDE + 4 * d4];
#pragma unroll
                for (int j = 0; j < 8; j++)
                    b[j] = *(const float4*)&eb[j * 16 * ES_STRIDE + 4 * d4];
#pragma unroll
                for (int i = 0; i < 8; i++)
#pragma unroll
                    for (int j = 0; j < 8; j++) {
                        acc[i][j] = __fmaf_rn(a[i].x, b[j].x, acc[i][j]);
                        acc[i][j] = __fmaf_rn(a[i].y, b[j].y, acc[i][j]);
                        acc[i][j] = __fmaf_rn(a[i].z, b[j].z, acc[i][j]);
                        acc[i][j] = __fmaf_rn(a[i].w, b[j].w, acc[i][j]);
                    }
            }
        }

        // Epilogue: t = fl( fl(x2 + e2) - 2*dot ), running min with earliest-k.
        float e2c[8];
#pragma unroll
        for (int j = 0; j < 8; j++) e2c[j] = __ldg(&g_e2[k0 + tx + 16 * j]);
#pragma unroll
        for (int i = 0; i < 8; i++) {
            float x2r = x2s[ty + 16 * i];
#pragma unroll
            for (int j = 0; j < 8; j++) {
                float S = __fadd_rn(x2r, e2c[j]);
                float t = __fadd_rn(S, -2.0f * acc[i][j]);   // 2*dot exact
                int  kk = k0 + tx + 16 * j;
                if (t < rmin[i]) { rmin[i] = t; rk[i] = kk; }
                else if (t == rmin[i] && kk < rk[i]) rk[i] = kk;
            }
        }
    }

    // Cross-thread (tx group of 16 lanes) reduce: min t, then min k (first-occurrence).
#pragma unroll
    for (int i = 0; i < 8; i++) {
        float t = rmin[i];
        int   k = rk[i];
#pragma unroll
        for (int o = 8; o; o >>= 1) {
            float to = __shfl_down_sync(0xffffffffu, t, o, 16);
            int   ko = __shfl_down_sync(0xffffffffu, k, o, 16);
            if (to < t || (to == t && ko < k)) { t = to; k = ko; }
        }
        if (tx == 0) g_codes[n0 + ty + 16 * i] = k;
    }
}

// ---------------------------------------------------------------------------
// Gather + z_q_st + per-row loss partials + codes output.
// ---------------------------------------------------------------------------
__global__ void vq_gather(const float* __restrict__ z_e, const float* __restrict__ emb,
                          float* __restrict__ out) {
    int row  = blockIdx.x;
    int d    = threadIdx.x;
    int code = g_codes[row];
    float ze = z_e[(size_t)row * DIM + d];
    float zq = emb[(size_t)code * DIM + d];
    float dif = __fsub_rn(zq, ze);
    out[(size_t)row * DIM + d] = __fadd_rn(ze, dif);   // z_q_st, exact ref rounding
    float sq = __fmul_rn(dif, dif);

    __shared__ float ws[8];
#pragma unroll
    for (int o = 16; o; o >>= 1) sq += __shfl_down_sync(0xffffffffu, sq, o);
    if ((d & 31) == 0) ws[d >> 5] = sq;
    __syncthreads();
    if (d == 0) {
        float s = 0.f;
#pragma unroll
        for (int w = 0; w < 8; w++) s += ws[w];
        g_part[row] = (double)s;
        out[(size_t)NROWS * DIM + 1 + row] = (float)code;
    }
}

__global__ void vq_loss(float* __restrict__ out) {
    __shared__ double sd[256];
    int tid = threadIdx.x;
    double s = 0.0;
    for (int i = tid; i < NROWS; i += 256) s += g_part[i];
    sd[tid] = s;
    __syncthreads();
    for (int st = 128; st; st >>= 1) {
        if (tid < st) sd[tid] += sd[tid + st];
        __syncthreads();
    }
    if (tid == 0) {
        float m = (float)(sd[0] / (double)((size_t)NROWS * DIM));
        out[(size_t)NROWS * DIM] = __fadd_rn(m, 0.25f * m);   // emb_loss + 0.25*commit
    }
}

// ---------------------------------------------------------------------------
extern "C" void kernel_launch(void* const* d_in, const int* in_sizes, int n_in,
                              void* d_out, int out_size) {
    const float* z_e = (const float*)d_in[0];
    const float* emb = (const float*)d_in[1];
    // Defensive: identify inputs by size in case metadata order differs.
    if (n_in >= 2 && in_sizes[0] == KCODES * DIM && in_sizes[1] == NROWS * DIM) {
        const float* t = z_e; z_e = emb; emb = t;
    }
    float* out = (float*)d_out;

    size_t smem = (size_t)(MT * ZS_STRIDE + NT * ES_STRIDE + MT) * sizeof(float);
    cudaFuncSetAttribute(vq_main, cudaFuncAttributeMaxDynamicSharedMemorySize, (int)smem);

    e2_kernel<<<KCODES / 8, 256>>>(emb);
    vq_main<<<NROWS / MT, 256, smem>>>(z_e, emb);
    vq_gather<<<NROWS, 256>>>(z_e, emb, out);
    vq_loss<<<1, 256>>>(out);
}